// round 2
// baseline (speedup 1.0000x reference)
#include <cuda_runtime.h>
#include <math.h>

#define SQ   1024      // sequence length
#define DM   2048      // model dim
#define NH   8         // heads
#define DKV  128       // head dim
#define HDIM 1024      // NH*DKV
#define NE   16        // experts
#define TOPK 6
#define FF   1408      // expert inter dim
#define FSH  2816      // shared expert inter dim

// ---------------- scratch (device globals; no runtime allocation) ----------------
__device__ float g_ln  [SQ*DM];
__device__ float g_q   [SQ*HDIM];
__device__ float g_k   [SQ*HDIM];
__device__ float g_v   [SQ*HDIM];
__device__ float g_sc  [NH*SQ*SQ];
__device__ float g_attn[SQ*HDIM];
__device__ float g_x2  [SQ*DM];
__device__ float g_ln2 [SQ*DM];
__device__ int   g_idx [SQ*TOPK];
__device__ float g_wt  [SQ*TOPK];
__device__ int   g_cnt [NE];
__device__ int   g_off [NE];
__device__ int   g_pos [NE];
__device__ int   g_tok [SQ*TOPK];
__device__ float g_wa  [SQ*TOPK];
__device__ float g_h   [SQ*TOPK*FF];
__device__ float g_hs  [SQ*FSH];

// ---------------- shared GEMM micro-kernel (64x64 tile, BK=16, 256 thr, 4x4) ------
__device__ __forceinline__ void mma_step(const float (*As)[64], const float (*Bs)[64],
                                         float acc[4][4], int ty4, int tx4)
{
#pragma unroll
    for (int kk = 0; kk < 16; kk++) {
        float a[4], b[4];
#pragma unroll
        for (int i = 0; i < 4; i++) a[i] = As[kk][ty4 + i];
#pragma unroll
        for (int j = 0; j < 4; j++) b[j] = Bs[kk][tx4 + j];
#pragma unroll
        for (int i = 0; i < 4; i++)
#pragma unroll
            for (int j = 0; j < 4; j++)
                acc[i][j] = fmaf(a[i], b[j], acc[i][j]);
    }
}

// C[M,N] = A[M,K] @ B[K,N] + bias (+ res). M,N %64==0, K %16==0.
__global__ __launch_bounds__(256) void gemm_bias_kernel(
    const float* __restrict__ A, const float* __restrict__ B,
    const float* __restrict__ bias, const float* __restrict__ res,
    float* __restrict__ C, int N, int Kd)
{
    __shared__ float As[16][64];
    __shared__ float Bs[16][64];
    const int bm = blockIdx.y * 64, bn = blockIdx.x * 64;
    const int tid = threadIdx.x;
    const int tx4 = (tid & 15) * 4, ty4 = (tid >> 4) * 4;
    const int am = tid >> 2, ak = (tid & 3) * 4;
    const int bkr = tid >> 4, bc = (tid & 15) * 4;
    float acc[4][4] = {};
    const float* Ap = A + (size_t)(bm + am) * Kd + ak;
    const float* Bp = B + (size_t)bkr * N + bn + bc;
    for (int k0 = 0; k0 < Kd; k0 += 16) {
        float4 a = *(const float4*)(Ap + k0);
        As[ak + 0][am] = a.x; As[ak + 1][am] = a.y;
        As[ak + 2][am] = a.z; As[ak + 3][am] = a.w;
        *(float4*)(&Bs[bkr][bc]) = *(const float4*)(Bp + (size_t)k0 * N);
        __syncthreads();
        mma_step(As, Bs, acc, ty4, tx4);
        __syncthreads();
    }
#pragma unroll
    for (int i = 0; i < 4; i++) {
        int r = bm + ty4 + i;
#pragma unroll
        for (int j = 0; j < 4; j++) {
            int c = bn + tx4 + j;
            float v = acc[i][j] + bias[c];
            if (res) v += res[(size_t)r * N + c];
            C[(size_t)r * N + c] = v;
        }
    }
}

// ---------------- layernorm (mean-subtract, weight only) --------------------------
__global__ __launch_bounds__(256) void ln_kernel(const float* __restrict__ x,
                                                 const float* __restrict__ g,
                                                 float* __restrict__ o)
{
    __shared__ float red[256];
    const int row = blockIdx.x, t = threadIdx.x;
    const float* xr = x + (size_t)row * DM;
    float s = 0.f;
    for (int i = t; i < DM; i += 256) s += xr[i];
    red[t] = s; __syncthreads();
    for (int k = 128; k > 0; k >>= 1) { if (t < k) red[t] += red[t + k]; __syncthreads(); }
    const float mu = red[0] * (1.f / DM); __syncthreads();
    float v = 0.f;
    for (int i = t; i < DM; i += 256) { float d0 = xr[i] - mu; v += d0 * d0; }
    red[t] = v; __syncthreads();
    for (int k = 128; k > 0; k >>= 1) { if (t < k) red[t] += red[t + k]; __syncthreads(); }
    const float inv = rsqrtf(red[0] * (1.f / DM) + 1e-8f);
    for (int i = t; i < DM; i += 256)
        o[(size_t)row * DM + i] = (xr[i] - mu) * inv * g[i];
}

// ---------------- attention scores: QK^T/sqrt(dk) + alibi + mask ------------------
__global__ __launch_bounds__(256) void score_kernel(const float* __restrict__ mask)
{
    __shared__ float As[16][64];
    __shared__ float Bs[16][64];
    const int h = blockIdx.z;
    const int bi = blockIdx.y * 64, bj = blockIdx.x * 64;
    const int tid = threadIdx.x;
    const int tx4 = (tid & 15) * 4, ty4 = (tid >> 4) * 4;
    const int am = tid >> 2, ak = (tid & 3) * 4;
    float acc[4][4] = {};
    const float* qp = g_q + (size_t)(bi + am) * HDIM + h * DKV + ak;
    const float* kp = g_k + (size_t)(bj + am) * HDIM + h * DKV + ak;
    for (int k0 = 0; k0 < DKV; k0 += 16) {
        float4 a = *(const float4*)(qp + k0);
        As[ak + 0][am] = a.x; As[ak + 1][am] = a.y;
        As[ak + 2][am] = a.z; As[ak + 3][am] = a.w;
        float4 b = *(const float4*)(kp + k0);
        Bs[ak + 0][am] = b.x; Bs[ak + 1][am] = b.y;
        Bs[ak + 2][am] = b.z; Bs[ak + 3][am] = b.w;
        __syncthreads();
        mma_step(As, Bs, acc, ty4, tx4);
        __syncthreads();
    }
    const float slope = exp2f(-(float)(h + 1));
    const float sc = 0.08838834764831845f;  // 1/sqrt(128)
#pragma unroll
    for (int i = 0; i < 4; i++) {
        int gi = bi + ty4 + i;
#pragma unroll
        for (int j = 0; j < 4; j++) {
            int gj = bj + tx4 + j;
            float al = (gi >= gj) ? -(float)(gi - gj) * slope : 0.f;
            g_sc[((size_t)h * SQ + gi) * SQ + gj] =
                acc[i][j] * sc + al + mask[(size_t)gi * SQ + gj];
        }
    }
}

// ---------------- row softmax over 1024 -------------------------------------------
__global__ __launch_bounds__(256) void softmax_kernel()
{
    __shared__ float red[256];
    float* r = g_sc + (size_t)blockIdx.x * SQ;
    const int t = threadIdx.x;
    float4 v = ((float4*)r)[t];
    float m = fmaxf(fmaxf(v.x, v.y), fmaxf(v.z, v.w));
    red[t] = m; __syncthreads();
    for (int k = 128; k > 0; k >>= 1) { if (t < k) red[t] = fmaxf(red[t], red[t + k]); __syncthreads(); }
    m = red[0]; __syncthreads();
    float4 e;
    e.x = __expf(v.x - m); e.y = __expf(v.y - m);
    e.z = __expf(v.z - m); e.w = __expf(v.w - m);
    red[t] = e.x + e.y + e.z + e.w; __syncthreads();
    for (int k = 128; k > 0; k >>= 1) { if (t < k) red[t] += red[t + k]; __syncthreads(); }
    const float inv = 1.f / red[0];
    e.x *= inv; e.y *= inv; e.z *= inv; e.w *= inv;
    ((float4*)r)[t] = e;
}

// ---------------- out = P^T @ V per head (reference's bShv einsum) -----------------
__global__ __launch_bounds__(256) void pv_kernel()
{
    __shared__ float As[16][64];
    __shared__ float Bs[16][64];
    const int h = blockIdx.z;
    const int bm = blockIdx.y * 64;   // j (output/key index)
    const int bn = blockIdx.x * 64;   // v
    const int tid = threadIdx.x;
    const int tx4 = (tid & 15) * 4, ty4 = (tid >> 4) * 4;
    const int bkr = tid >> 4, bc = (tid & 15) * 4;
    float acc[4][4] = {};
    const float* Pp = g_sc + (size_t)h * SQ * SQ + (size_t)bkr * SQ + bm + bc;
    const float* Vp = g_v + (size_t)bkr * HDIM + h * DKV + bn + bc;
    for (int k0 = 0; k0 < SQ; k0 += 16) {
        *(float4*)(&As[bkr][bc]) = *(const float4*)(Pp + (size_t)k0 * SQ);
        *(float4*)(&Bs[bkr][bc]) = *(const float4*)(Vp + (size_t)k0 * HDIM);
        __syncthreads();
        mma_step(As, Bs, acc, ty4, tx4);
        __syncthreads();
    }
#pragma unroll
    for (int i = 0; i < 4; i++)
#pragma unroll
        for (int j = 0; j < 4; j++)
            g_attn[(size_t)(bm + ty4 + i) * HDIM + h * DKV + bn + tx4 + j] = acc[i][j];
}

// ---------------- MoE gate: logits, softmax, top-6, counts -------------------------
__global__ void reset_kernel()
{
    int t = threadIdx.x;
    if (t < NE) { g_cnt[t] = 0; g_pos[t] = 0; }
}

__global__ __launch_bounds__(256) void gate_kernel(const float* __restrict__ xf,
                                                   const float* __restrict__ gw,
                                                   const float* __restrict__ gb)
{
    __shared__ float xs[DM];
    __shared__ float lg[NE];
    const int tok = blockIdx.x, tid = threadIdx.x;
    for (int i = tid; i < DM; i += 256) xs[i] = xf[(size_t)tok * DM + i];
    __syncthreads();
    const int warp = tid >> 5, lane = tid & 31;
    for (int e = warp; e < NE; e += 8) {
        const float* w = gw + (size_t)e * DM;
        float s = 0.f;
        for (int i = lane; i < DM; i += 32) s += xs[i] * w[i];
        for (int o = 16; o; o >>= 1) s += __shfl_down_sync(0xFFFFFFFFu, s, o);
        if (lane == 0) lg[e] = s;
    }
    __syncthreads();
    if (tid == 0) {
        float mx = -1e30f;
        for (int e = 0; e < NE; e++) mx = fmaxf(mx, lg[e]);
        float sm[NE], se = 0.f;
        for (int e = 0; e < NE; e++) { sm[e] = expf(lg[e] - mx); se += sm[e]; }
        float inv = 1.f / se;
        for (int e = 0; e < NE; e++) sm[e] *= inv;
        bool used[NE] = {};
        for (int kk = 0; kk < TOPK; kk++) {
            float best = -1e30f; int bi = 0;
            for (int e = 0; e < NE; e++) {
                if (!used[e]) {
                    float s = sm[e] + gb[e];
                    if (s > best) { best = s; bi = e; }
                }
            }
            used[bi] = true;
            g_idx[tok * TOPK + kk] = bi;
            g_wt[tok * TOPK + kk] = sm[bi];
            atomicAdd(&g_cnt[bi], 1);
        }
    }
}

__global__ void scan_kernel()
{
    int r = 0;
    for (int e = 0; e < NE; e++) { g_off[e] = r; r += g_cnt[e]; }
}

__global__ __launch_bounds__(256) void place_kernel()
{
    int t = blockIdx.x * 256 + threadIdx.x;
    if (t >= SQ) return;
    for (int kk = 0; kk < TOPK; kk++) {
        int e = g_idx[t * TOPK + kk];
        int p = g_off[e] + atomicAdd(&g_pos[e], 1);
        g_tok[p] = t;
        g_wa[p] = g_wt[t * TOPK + kk];
    }
}

// ---------------- shared-expert up: H = silu(A@W1+b1)*(A@W3+b3) --------------------
__global__ __launch_bounds__(256) void swiglu_kernel(
    const float* __restrict__ A,
    const float* __restrict__ W1, const float* __restrict__ b1,
    const float* __restrict__ W3, const float* __restrict__ b3,
    float* __restrict__ Hout, int N, int Kd)
{
    __shared__ float As[16][64];
    __shared__ float B1s[16][64];
    __shared__ float B3s[16][64];
    const int bm = blockIdx.y * 64, bn = blockIdx.x * 64;
    const int tid = threadIdx.x;
    const int tx4 = (tid & 15) * 4, ty4 = (tid >> 4) * 4;
    const int am = tid >> 2, ak = (tid & 3) * 4;
    const int bkr = tid >> 4, bc = (tid & 15) * 4;
    float acc1[4][4] = {}, acc3[4][4] = {};
    const float* Ap = A + (size_t)(bm + am) * Kd + ak;
    const float* B1p = W1 + (size_t)bkr * N + bn + bc;
    const float* B3p = W3 + (size_t)bkr * N + bn + bc;
    for (int k0 = 0; k0 < Kd; k0 += 16) {
        float4 a = *(const float4*)(Ap + k0);
        As[ak + 0][am] = a.x; As[ak + 1][am] = a.y;
        As[ak + 2][am] = a.z; As[ak + 3][am] = a.w;
        *(float4*)(&B1s[bkr][bc]) = *(const float4*)(B1p + (size_t)k0 * N);
        *(float4*)(&B3s[bkr][bc]) = *(const float4*)(B3p + (size_t)k0 * N);
        __syncthreads();
        mma_step(As, B1s, acc1, ty4, tx4);
        mma_step(As, B3s, acc3, ty4, tx4);
        __syncthreads();
    }
#pragma unroll
    for (int i = 0; i < 4; i++) {
        int r = bm + ty4 + i;
#pragma unroll
        for (int j = 0; j < 4; j++) {
            int c = bn + tx4 + j;
            float v1 = acc1[i][j] + b1[c];
            float v3 = acc3[i][j] + b3[c];
            Hout[(size_t)r * N + c] = v1 / (1.f + __expf(-v1)) * v3;
        }
    }
}

// ---------------- routed experts up (gathered tokens) ------------------------------
__global__ __launch_bounds__(256) void moe_up_kernel(
    const float* __restrict__ W1, const float* __restrict__ B1,
    const float* __restrict__ W3, const float* __restrict__ B3)
{
    const int e = blockIdx.z;
    const int count = g_cnt[e];
    const int bm = blockIdx.y * 64;
    if (bm >= count) return;
    const int bn = blockIdx.x * 64;
    const int base = g_off[e];
    __shared__ float As[16][64];
    __shared__ float B1s[16][64];
    __shared__ float B3s[16][64];
    const int tid = threadIdx.x;
    const int tx4 = (tid & 15) * 4, ty4 = (tid >> 4) * 4;
    const int am = tid >> 2, ak = (tid & 3) * 4;
    const int bkr = tid >> 4, bc = (tid & 15) * 4;
    const int rowv = bm + am;
    const bool valid = rowv < count;
    const int token = valid ? g_tok[base + rowv] : 0;
    const float* Ap = g_ln2 + (size_t)token * DM + ak;
    const float* B1p = W1 + (size_t)e * DM * FF + (size_t)bkr * FF + bn + bc;
    const float* B3p = W3 + (size_t)e * DM * FF + (size_t)bkr * FF + bn + bc;
    float acc1[4][4] = {}, acc3[4][4] = {};
    for (int k0 = 0; k0 < DM; k0 += 16) {
        float4 a = valid ? *(const float4*)(Ap + k0) : make_float4(0.f, 0.f, 0.f, 0.f);
        As[ak + 0][am] = a.x; As[ak + 1][am] = a.y;
        As[ak + 2][am] = a.z; As[ak + 3][am] = a.w;
        *(float4*)(&B1s[bkr][bc]) = *(const float4*)(B1p + (size_t)k0 * FF);
        *(float4*)(&B3s[bkr][bc]) = *(const float4*)(B3p + (size_t)k0 * FF);
        __syncthreads();
        mma_step(As, B1s, acc1, ty4, tx4);
        mma_step(As, B3s, acc3, ty4, tx4);
        __syncthreads();
    }
#pragma unroll
    for (int i = 0; i < 4; i++) {
        int r = bm + ty4 + i;
        if (r < count) {
            int slot = base + r;
#pragma unroll
            for (int j = 0; j < 4; j++) {
                int c = bn + tx4 + j;
                float v1 = acc1[i][j] + B1[(size_t)e * FF + c];
                float v3 = acc3[i][j] + B3[(size_t)e * FF + c];
                g_h[(size_t)slot * FF + c] = v1 / (1.f + __expf(-v1)) * v3;
            }
        }
    }
}

// ---------------- routed experts down + weighted scatter ---------------------------
__global__ __launch_bounds__(256) void moe_down_kernel(
    const float* __restrict__ W2, const float* __restrict__ B2,
    float* __restrict__ out)
{
    const int e = blockIdx.z;
    const int count = g_cnt[e];
    const int bm = blockIdx.y * 64;
    if (bm >= count) return;
    const int bn = blockIdx.x * 64;
    const int base = g_off[e];
    __shared__ float As[16][64];
    __shared__ float Bs[16][64];
    const int tid = threadIdx.x;
    const int tx4 = (tid & 15) * 4, ty4 = (tid >> 4) * 4;
    const int am = tid >> 2, ak = (tid & 3) * 4;
    const int bkr = tid >> 4, bc = (tid & 15) * 4;
    const int rowv = bm + am;
    const int slot = (rowv < count) ? base + rowv : 0;  // slot 0 always exists
    const float* Ap = g_h + (size_t)slot * FF + ak;
    const float* Bp = W2 + (size_t)e * FF * DM + (size_t)bkr * DM + bn + bc;
    float acc[4][4] = {};
    for (int k0 = 0; k0 < FF; k0 += 16) {
        float4 a = *(const float4*)(Ap + k0);
        As[ak + 0][am] = a.x; As[ak + 1][am] = a.y;
        As[ak + 2][am] = a.z; As[ak + 3][am] = a.w;
        *(float4*)(&Bs[bkr][bc]) = *(const float4*)(Bp + (size_t)k0 * DM);
        __syncthreads();
        mma_step(As, Bs, acc, ty4, tx4);
        __syncthreads();
    }
#pragma unroll
    for (int i = 0; i < 4; i++) {
        int r = bm + ty4 + i;
        if (r < count) {
            int s2 = base + r;
            int token = g_tok[s2];
            float wv = g_wa[s2];
#pragma unroll
            for (int j = 0; j < 4; j++) {
                int c = bn + tx4 + j;
                atomicAdd(&out[(size_t)token * DM + c],
                          wv * (acc[i][j] + B2[(size_t)e * DM + c]));
            }
        }
    }
}

// ---------------- launcher ---------------------------------------------------------
extern "C" void kernel_launch(void* const* d_in, const int* in_sizes, int n_in,
                              void* d_out, int out_size)
{
    const float* x      = (const float*)d_in[0];
    const float* mask   = (const float*)d_in[1];
    const float* attn_g = (const float*)d_in[2];
    const float* wq_w   = (const float*)d_in[3];
    const float* wq_b   = (const float*)d_in[4];
    const float* wk_w   = (const float*)d_in[5];
    const float* wk_b   = (const float*)d_in[6];
    const float* wv_w   = (const float*)d_in[7];
    const float* wv_b   = (const float*)d_in[8];
    const float* wo_w   = (const float*)d_in[9];
    const float* wo_b   = (const float*)d_in[10];
    const float* ffn_g  = (const float*)d_in[11];
    const float* gate_w = (const float*)d_in[12];
    const float* gate_b = (const float*)d_in[13];
    const float* e_w1   = (const float*)d_in[14];
    const float* e_b1   = (const float*)d_in[15];
    const float* e_w2   = (const float*)d_in[16];
    const float* e_b2   = (const float*)d_in[17];
    const float* e_w3   = (const float*)d_in[18];
    const float* e_b3   = (const float*)d_in[19];
    const float* s_w1   = (const float*)d_in[20];
    const float* s_b1   = (const float*)d_in[21];
    const float* s_w2   = (const float*)d_in[22];
    const float* s_b2   = (const float*)d_in[23];
    const float* s_w3   = (const float*)d_in[24];
    const float* s_b3   = (const float*)d_in[25];
    float* outp = (float*)d_out;

    float *p_ln, *p_q, *p_k, *p_v, *p_attn, *p_x2, *p_ln2, *p_hs;
    cudaGetSymbolAddress((void**)&p_ln,   g_ln);
    cudaGetSymbolAddress((void**)&p_q,    g_q);
    cudaGetSymbolAddress((void**)&p_k,    g_k);
    cudaGetSymbolAddress((void**)&p_v,    g_v);
    cudaGetSymbolAddress((void**)&p_attn, g_attn);
    cudaGetSymbolAddress((void**)&p_x2,   g_x2);
    cudaGetSymbolAddress((void**)&p_ln2,  g_ln2);
    cudaGetSymbolAddress((void**)&p_hs,   g_hs);

    // 1) attention branch
    ln_kernel<<<SQ, 256>>>(x, attn_g, p_ln);
    gemm_bias_kernel<<<dim3(HDIM/64, SQ/64), 256>>>(p_ln, wq_w, wq_b, nullptr, p_q, HDIM, DM);
    gemm_bias_kernel<<<dim3(HDIM/64, SQ/64), 256>>>(p_ln, wk_w, wk_b, nullptr, p_k, HDIM, DM);
    gemm_bias_kernel<<<dim3(HDIM/64, SQ/64), 256>>>(p_ln, wv_w, wv_b, nullptr, p_v, HDIM, DM);
    score_kernel<<<dim3(SQ/64, SQ/64, NH), 256>>>(mask);
    softmax_kernel<<<NH*SQ, 256>>>();
    pv_kernel<<<dim3(DKV/64, SQ/64, NH), 256>>>();
    gemm_bias_kernel<<<dim3(DM/64, SQ/64), 256>>>(p_attn, wo_w, wo_b, x, p_x2, DM, HDIM);

    // 2) MoE branch
    ln_kernel<<<SQ, 256>>>(p_x2, ffn_g, p_ln2);
    reset_kernel<<<1, 32>>>();
    gate_kernel<<<SQ, 256>>>(p_ln2, gate_w, gate_b);
    scan_kernel<<<1, 1>>>();
    place_kernel<<<(SQ + 255)/256, 256>>>();

    // shared expert: d_out = x2 + shared_mlp(ln2)
    swiglu_kernel<<<dim3(FSH/64, SQ/64), 256>>>(p_ln2, s_w1, s_b1, s_w3, s_b3, p_hs, FSH, DM);
    gemm_bias_kernel<<<dim3(DM/64, SQ/64), 256>>>(p_hs, s_w2, s_b2, p_x2, outp, DM, FSH);

    // routed experts: d_out += sum_e w * expert_e(ln2)
    moe_up_kernel<<<dim3(FF/64, SQ/64, NE), 256>>>(e_w1, e_b1, e_w3, e_b3);
    moe_down_kernel<<<dim3(DM/64, SQ/64, NE), 256>>>(e_w2, e_b2, outp);
}

// round 4
// speedup vs baseline: 2.8537x; 2.8537x over previous
#include <cuda_runtime.h>
#include <cstdint>
#include <math.h>

#define SQ 1024
#define DM 2048
#define NH 8
#define DKV 128
#define HDIM 1024
#define NE 16
#define TOPK 6
#define FF 1408
#define FSH 2816
#define NSLOT (SQ*TOPK)

__device__ float g_ln[SQ*DM];
__device__ float g_q[SQ*HDIM];
__device__ float g_k[SQ*HDIM];
__device__ float g_v[SQ*HDIM];
__device__ float g_sc[NH*SQ*SQ];
__device__ float g_attn[SQ*HDIM];
__device__ float g_x2[SQ*DM];
__device__ float g_ln2[SQ*DM];
__device__ float g_t1[SQ*FSH];
__device__ float g_t3[SQ*FSH];
__device__ float g_hs[SQ*FSH];
__device__ float g_h1[NSLOT*FF];
__device__ float g_h3[NSLOT*FF];
__device__ float g_hh[NSLOT*FF];
__device__ int   g_idx[SQ*TOPK];
__device__ float g_wt[SQ*TOPK];
__device__ int   g_cnt[NE];
__device__ int   g_off[NE];
__device__ int   g_pos[NE];
__device__ int   g_tok[NSLOT];
__device__ float g_wa[NSLOT];

struct QKV3 { const float* B[3]; const float* Bb[3]; float* C[3]; };

__device__ __forceinline__ uint32_t smem_u32(const void* p){
    uint32_t a;
    asm("{ .reg .u64 t; cvta.to.shared.u64 t, %1; cvt.u32.u64 %0, t; }":"=r"(a):"l"(p));
    return a;
}
__device__ __forceinline__ uint32_t f2tf(float f){
    uint32_t u; asm("cvt.rna.tf32.f32 %0,%1;":"=r"(u):"f"(f)); return u;
}
__device__ __forceinline__ void cpa16(uint32_t dst, const void* src, int sz){
    asm volatile("cp.async.cg.shared.global [%0],[%1],16,%2;"
                 ::"r"(dst),"l"(src),"r"(sz):"memory");
}
__device__ __forceinline__ void mma8(float* c, const uint32_t* a, const uint32_t* b){
    asm volatile("mma.sync.aligned.m16n8k8.row.col.f32.tf32.tf32.f32 "
        "{%0,%1,%2,%3},{%4,%5,%6,%7},{%8,%9},{%0,%1,%2,%3};"
        :"+f"(c[0]),"+f"(c[1]),"+f"(c[2]),"+f"(c[3])
        :"r"(a[0]),"r"(a[1]),"r"(a[2]),"r"(a[3]),"r"(b[0]),"r"(b[1]));
}

// smem layout: A buffers stride 36 floats (144B/row), B stride 136 floats (544B/k-row)
#define AS_STRIDE 36
#define BS_STRIDE 136
#define A_BUF_BYTES (128*AS_STRIDE*4)   // 18432
#define B_BUF_BYTES (32*BS_STRIDE*4)    // 17408
#define DSM (2*A_BUF_BYTES + 2*B_BUF_BYTES)  // 71680

// MODE 0: plain (+bias, optional residual). MODE 1: token-gather A -> slot store.
// MODE 2: slot A -> weighted atomic scatter. MODE 3: QKV fused (z selects B/bias/C).
// CTA tile 128x128, K-chunk 32, double-buffered cp.async, warp grid 4(m) x 2(n).
template<int MODE>
__global__ __launch_bounds__(256,1) void tc_gemm(
    const float* __restrict__ A, const float* __restrict__ B,
    const float* __restrict__ bias, const float* __restrict__ res,
    float* __restrict__ C, int N, int Kd, QKV3 q3)
{
    extern __shared__ __align__(16) char sm[];
    const int tid = threadIdx.x, wid = tid>>5, lane = tid&31;
    const int warp_m = wid&3, warp_n = wid>>2;
    const int bm = blockIdx.y*128, bn = blockIdx.x*128;
    int count = 1<<30, base = 0;
    if (MODE == 1 || MODE == 2){
        int e = blockIdx.z;
        count = g_cnt[e]; base = g_off[e];
        if (bm >= count) return;
        B    += (size_t)e*Kd*N;
        bias += (size_t)e*N;
    }
    if (MODE == 3){
        int z = blockIdx.z;
        B = q3.B[z]; bias = q3.Bb[z]; C = q3.C[z];
    }
    // A row pointers (4 rows per thread: (tid>>3)+32i), validity for zero-fill
    const float* ap[4]; int av[4];
#pragma unroll
    for (int i = 0; i < 4; i++){
        int r = (tid>>3) + 32*i, row = bm + r;
        av[i] = 16;
        if (MODE == 1){
            bool v = row < count;
            av[i] = v ? 16 : 0;
            ap[i] = A + (size_t)(v ? g_tok[base+row] : 0)*Kd;
        } else if (MODE == 2){
            ap[i] = A + (size_t)(base + (row < count ? row : count-1))*Kd;
        } else ap[i] = A + (size_t)row*Kd;
    }
    const uint32_t smu = smem_u32(sm);
    const int aq = (tid&7)*4;          // A: k quad within chunk
    const uint32_t a_dst0 = smu + (uint32_t)((tid>>3))*144u + (uint32_t)aq*4u;
    const int bk = tid>>5, bnq = (tid&31)*4;   // B: k row, n quad
    const uint32_t b_dst0 = smu + 2u*A_BUF_BYTES + (uint32_t)bk*544u + (uint32_t)bnq*4u;

    const int nch = Kd/32;
    // prologue: chunk 0 -> buf 0
    {
        int k0 = 0;
#pragma unroll
        for (int i = 0; i < 4; i++)
            cpa16(a_dst0 + (uint32_t)i*32u*144u, ap[i] + k0 + aq, av[i]);
#pragma unroll
        for (int i = 0; i < 4; i++)
            cpa16(b_dst0 + (uint32_t)i*8u*544u, B + (size_t)(k0+bk+8*i)*N + bn + bnq, 16);
        asm volatile("cp.async.commit_group;":::"memory");
    }
    float acc[2][8][4];
#pragma unroll
    for (int mt = 0; mt < 2; mt++)
#pragma unroll
        for (int nt = 0; nt < 8; nt++)
#pragma unroll
            for (int r = 0; r < 4; r++) acc[mt][nt][r] = 0.f;

    const int qr = lane>>2, qc = lane&3;
    for (int c = 0; c < nch; c++){
        const int buf = c & 1;
        if (c+1 < nch){
            const int nb = (c+1)&1, k0 = (c+1)*32;
#pragma unroll
            for (int i = 0; i < 4; i++)
                cpa16(a_dst0 + (uint32_t)nb*A_BUF_BYTES + (uint32_t)i*32u*144u,
                      ap[i] + k0 + aq, av[i]);
#pragma unroll
            for (int i = 0; i < 4; i++)
                cpa16(b_dst0 + (uint32_t)nb*B_BUF_BYTES + (uint32_t)i*8u*544u,
                      B + (size_t)(k0+bk+8*i)*N + bn + bnq, 16);
            asm volatile("cp.async.commit_group;":::"memory");
            asm volatile("cp.async.wait_group 1;":::"memory");
        } else {
            asm volatile("cp.async.wait_group 0;":::"memory");
        }
        __syncthreads();
        const float* Af = (const float*)(sm + buf*A_BUF_BYTES);
        const float* Bf = (const float*)(sm + 2*A_BUF_BYTES + buf*B_BUF_BYTES);
#pragma unroll
        for (int ks = 0; ks < 4; ks++){
            uint32_t afr[2][4];
#pragma unroll
            for (int mt = 0; mt < 2; mt++){
                int rb = warp_m*32 + mt*16 + qr;
                int kb = ks*8 + qc;
                afr[mt][0] = f2tf(Af[rb*AS_STRIDE + kb]);
                afr[mt][1] = f2tf(Af[(rb+8)*AS_STRIDE + kb]);
                afr[mt][2] = f2tf(Af[rb*AS_STRIDE + kb + 4]);
                afr[mt][3] = f2tf(Af[(rb+8)*AS_STRIDE + kb + 4]);
            }
#pragma unroll
            for (int nt = 0; nt < 8; nt++){
                uint32_t bfr[2];
                int nb = warp_n*64 + nt*8 + qr;
                int kb = ks*8 + qc;
                bfr[0] = f2tf(Bf[kb*BS_STRIDE + nb]);
                bfr[1] = f2tf(Bf[(kb+4)*BS_STRIDE + nb]);
                mma8(acc[0][nt], afr[0], bfr);
                mma8(acc[1][nt], afr[1], bfr);
            }
        }
        __syncthreads();
    }

    // epilogue
#pragma unroll
    for (int mt = 0; mt < 2; mt++){
#pragma unroll
        for (int half = 0; half < 2; half++){
            int rl = warp_m*32 + mt*16 + qr + half*8;     // local row
            bool rv = true; size_t crow = (size_t)(bm + rl); float ws = 1.f;
            if (MODE == 1){ rv = (bm + rl) < count; crow = (size_t)(base + bm + rl); }
            if (MODE == 2){
                rv = (bm + rl) < count;
                int s2 = rv ? (base + bm + rl) : base;
                crow = (size_t)g_tok[s2]; ws = g_wa[s2];
            }
            if (!rv) continue;
#pragma unroll
            for (int nt = 0; nt < 8; nt++){
                int col = bn + warp_n*64 + nt*8 + qc*2;
                float v0 = acc[mt][nt][half*2+0] + bias[col];
                float v1 = acc[mt][nt][half*2+1] + bias[col+1];
                if (MODE == 2){
                    atomicAdd(C + crow*N + col,     ws*v0);
                    atomicAdd(C + crow*N + col + 1, ws*v1);
                } else {
                    if (MODE == 0 && res){
                        v0 += res[crow*N + col];
                        v1 += res[crow*N + col + 1];
                    }
                    *(float2*)(C + crow*N + col) = make_float2(v0, v1);
                }
            }
        }
    }
}

// ---------------- SIMT parts ----------------
__device__ __forceinline__ void mma_step(const float (*As)[64], const float (*Bs)[64],
                                         float acc[4][4], int ty4, int tx4)
{
#pragma unroll
    for (int kk = 0; kk < 16; kk++){
        float a[4], b[4];
#pragma unroll
        for (int i = 0; i < 4; i++) a[i] = As[kk][ty4+i];
#pragma unroll
        for (int j = 0; j < 4; j++) b[j] = Bs[kk][tx4+j];
#pragma unroll
        for (int i = 0; i < 4; i++)
#pragma unroll
            for (int j = 0; j < 4; j++) acc[i][j] = fmaf(a[i], b[j], acc[i][j]);
    }
}

__global__ __launch_bounds__(256) void ln_kernel(const float* __restrict__ x,
                                                 const float* __restrict__ g,
                                                 float* __restrict__ o)
{
    __shared__ float red[256];
    const int row = blockIdx.x, t = threadIdx.x;
    const float* xr = x + (size_t)row*DM;
    float s = 0.f;
    for (int i = t; i < DM; i += 256) s += xr[i];
    red[t] = s; __syncthreads();
    for (int k = 128; k > 0; k >>= 1){ if (t < k) red[t] += red[t+k]; __syncthreads(); }
    const float mu = red[0]*(1.f/DM); __syncthreads();
    float v = 0.f;
    for (int i = t; i < DM; i += 256){ float d0 = xr[i]-mu; v += d0*d0; }
    red[t] = v; __syncthreads();
    for (int k = 128; k > 0; k >>= 1){ if (t < k) red[t] += red[t+k]; __syncthreads(); }
    const float inv = rsqrtf(red[0]*(1.f/DM) + 1e-8f);
    for (int i = t; i < DM; i += 256) o[(size_t)row*DM+i] = (xr[i]-mu)*inv*g[i];
}

__global__ __launch_bounds__(256) void score_kernel(const float* __restrict__ mask)
{
    __shared__ float As[16][64];
    __shared__ float Bs[16][64];
    const int h = blockIdx.z, bi = blockIdx.y*64, bj = blockIdx.x*64;
    const int tid = threadIdx.x;
    const int tx4 = (tid&15)*4, ty4 = (tid>>4)*4;
    const int am = tid>>2, ak = (tid&3)*4;
    float acc[4][4] = {};
    const float* qp = g_q + (size_t)(bi+am)*HDIM + h*DKV + ak;
    const float* kp = g_k + (size_t)(bj+am)*HDIM + h*DKV + ak;
    for (int k0 = 0; k0 < DKV; k0 += 16){
        float4 a = *(const float4*)(qp+k0);
        As[ak+0][am]=a.x; As[ak+1][am]=a.y; As[ak+2][am]=a.z; As[ak+3][am]=a.w;
        float4 b = *(const float4*)(kp+k0);
        Bs[ak+0][am]=b.x; Bs[ak+1][am]=b.y; Bs[ak+2][am]=b.z; Bs[ak+3][am]=b.w;
        __syncthreads();
        mma_step(As, Bs, acc, ty4, tx4);
        __syncthreads();
    }
    const float slope = exp2f(-(float)(h+1));
    const float sc = 0.08838834764831845f;
#pragma unroll
    for (int i = 0; i < 4; i++){
        int gi = bi+ty4+i;
#pragma unroll
        for (int j = 0; j < 4; j++){
            int gj = bj+tx4+j;
            float al = (gi >= gj) ? -(float)(gi-gj)*slope : 0.f;
            g_sc[((size_t)h*SQ+gi)*SQ+gj] = acc[i][j]*sc + al + mask[(size_t)gi*SQ+gj];
        }
    }
}

__global__ __launch_bounds__(256) void softmax_kernel()
{
    __shared__ float red[256];
    float* r = g_sc + (size_t)blockIdx.x*SQ;
    const int t = threadIdx.x;
    float4 v = ((float4*)r)[t];
    float m = fmaxf(fmaxf(v.x,v.y), fmaxf(v.z,v.w));
    red[t] = m; __syncthreads();
    for (int k = 128; k > 0; k >>= 1){ if (t < k) red[t] = fmaxf(red[t], red[t+k]); __syncthreads(); }
    m = red[0]; __syncthreads();
    float4 e;
    e.x=__expf(v.x-m); e.y=__expf(v.y-m); e.z=__expf(v.z-m); e.w=__expf(v.w-m);
    red[t] = e.x+e.y+e.z+e.w; __syncthreads();
    for (int k = 128; k > 0; k >>= 1){ if (t < k) red[t] += red[t+k]; __syncthreads(); }
    const float inv = 1.f/red[0];
    e.x*=inv; e.y*=inv; e.z*=inv; e.w*=inv;
    ((float4*)r)[t] = e;
}

__global__ __launch_bounds__(256) void pv_kernel()
{
    __shared__ float As[16][64];
    __shared__ float Bs[16][64];
    const int h = blockIdx.z, bm = blockIdx.y*64, bn = blockIdx.x*64;
    const int tid = threadIdx.x;
    const int tx4 = (tid&15)*4, ty4 = (tid>>4)*4;
    const int bkr = tid>>4, bc = (tid&15)*4;
    float acc[4][4] = {};
    const float* Pp = g_sc + (size_t)h*SQ*SQ + (size_t)bkr*SQ + bm + bc;
    const float* Vp = g_v + (size_t)bkr*HDIM + h*DKV + bn + bc;
    for (int k0 = 0; k0 < SQ; k0 += 16){
        *(float4*)(&As[bkr][bc]) = *(const float4*)(Pp + (size_t)k0*SQ);
        *(float4*)(&Bs[bkr][bc]) = *(const float4*)(Vp + (size_t)k0*HDIM);
        __syncthreads();
        mma_step(As, Bs, acc, ty4, tx4);
        __syncthreads();
    }
#pragma unroll
    for (int i = 0; i < 4; i++)
#pragma unroll
        for (int j = 0; j < 4; j++)
            g_attn[(size_t)(bm+ty4+i)*HDIM + h*DKV + bn+tx4+j] = acc[i][j];
}

__global__ void reset_kernel(){
    int t = threadIdx.x;
    if (t < NE){ g_cnt[t] = 0; g_pos[t] = 0; }
}

__global__ __launch_bounds__(256) void gate_kernel(const float* __restrict__ xf,
                                                   const float* __restrict__ gw,
                                                   const float* __restrict__ gb)
{
    __shared__ float xs[DM];
    __shared__ float lg[NE];
    const int tok = blockIdx.x, tid = threadIdx.x;
    for (int i = tid; i < DM; i += 256) xs[i] = xf[(size_t)tok*DM+i];
    __syncthreads();
    const int warp = tid>>5, lane = tid&31;
    for (int e = warp; e < NE; e += 8){
        const float* w = gw + (size_t)e*DM;
        float s = 0.f;
        for (int i = lane; i < DM; i += 32) s += xs[i]*w[i];
        for (int o = 16; o; o >>= 1) s += __shfl_down_sync(0xFFFFFFFFu, s, o);
        if (lane == 0) lg[e] = s;
    }
    __syncthreads();
    if (tid == 0){
        float mx = -1e30f;
        for (int e = 0; e < NE; e++) mx = fmaxf(mx, lg[e]);
        float sm[NE], se = 0.f;
        for (int e = 0; e < NE; e++){ sm[e] = expf(lg[e]-mx); se += sm[e]; }
        float inv = 1.f/se;
        for (int e = 0; e < NE; e++) sm[e] *= inv;
        bool used[NE] = {};
        for (int kk = 0; kk < TOPK; kk++){
            float best = -1e30f; int bi = 0;
            for (int e = 0; e < NE; e++)
                if (!used[e]){ float s = sm[e]+gb[e]; if (s > best){ best = s; bi = e; } }
            used[bi] = true;
            g_idx[tok*TOPK+kk] = bi;
            g_wt[tok*TOPK+kk] = sm[bi];
            atomicAdd(&g_cnt[bi], 1);
        }
    }
}

__global__ void scan_kernel(){
    int r = 0;
    for (int e = 0; e < NE; e++){ g_off[e] = r; r += g_cnt[e]; }
}

__global__ __launch_bounds__(256) void place_kernel(){
    int t = blockIdx.x*256 + threadIdx.x;
    if (t >= SQ) return;
    for (int kk = 0; kk < TOPK; kk++){
        int e = g_idx[t*TOPK+kk];
        int p = g_off[e] + atomicAdd(&g_pos[e], 1);
        g_tok[p] = t;
        g_wa[p] = g_wt[t*TOPK+kk];
    }
}

__global__ __launch_bounds__(256) void silu_mul_kernel(const float* __restrict__ a,
                                                       const float* __restrict__ b,
                                                       float* __restrict__ o, int n4)
{
    int i = blockIdx.x*256 + threadIdx.x;
    if (i >= n4) return;
    float4 va = ((const float4*)a)[i];
    float4 vb = ((const float4*)b)[i];
    float4 vo;
    vo.x = va.x/(1.f+__expf(-va.x))*vb.x;
    vo.y = va.y/(1.f+__expf(-va.y))*vb.y;
    vo.z = va.z/(1.f+__expf(-va.z))*vb.z;
    vo.w = va.w/(1.f+__expf(-va.w))*vb.w;
    ((float4*)o)[i] = vo;
}

extern "C" void kernel_launch(void* const* d_in, const int* in_sizes, int n_in,
                              void* d_out, int out_size)
{
    const float* x      = (const float*)d_in[0];
    const float* mask   = (const float*)d_in[1];
    const float* attn_g = (const float*)d_in[2];
    const float* wq_w   = (const float*)d_in[3];
    const float* wq_b   = (const float*)d_in[4];
    const float* wk_w   = (const float*)d_in[5];
    const float* wk_b   = (const float*)d_in[6];
    const float* wv_w   = (const float*)d_in[7];
    const float* wv_b   = (const float*)d_in[8];
    const float* wo_w   = (const float*)d_in[9];
    const float* wo_b   = (const float*)d_in[10];
    const float* ffn_g  = (const float*)d_in[11];
    const float* gate_w = (const float*)d_in[12];
    const float* gate_b = (const float*)d_in[13];
    const float* e_w1   = (const float*)d_in[14];
    const float* e_b1   = (const float*)d_in[15];
    const float* e_w2   = (const float*)d_in[16];
    const float* e_b2   = (const float*)d_in[17];
    const float* e_w3   = (const float*)d_in[18];
    const float* e_b3   = (const float*)d_in[19];
    const float* s_w1   = (const float*)d_in[20];
    const float* s_b1   = (const float*)d_in[21];
    const float* s_w2   = (const float*)d_in[22];
    const float* s_b2   = (const float*)d_in[23];
    const float* s_w3   = (const float*)d_in[24];
    const float* s_b3   = (const float*)d_in[25];
    float* outp = (float*)d_out;

    float *p_ln,*p_q,*p_k,*p_v,*p_attn,*p_x2,*p_ln2,*p_t1,*p_t3,*p_hs,*p_h1,*p_h3,*p_hh;
    cudaGetSymbolAddress((void**)&p_ln,  g_ln);
    cudaGetSymbolAddress((void**)&p_q,   g_q);
    cudaGetSymbolAddress((void**)&p_k,   g_k);
    cudaGetSymbolAddress((void**)&p_v,   g_v);
    cudaGetSymbolAddress((void**)&p_attn,g_attn);
    cudaGetSymbolAddress((void**)&p_x2,  g_x2);
    cudaGetSymbolAddress((void**)&p_ln2, g_ln2);
    cudaGetSymbolAddress((void**)&p_t1,  g_t1);
    cudaGetSymbolAddress((void**)&p_t3,  g_t3);
    cudaGetSymbolAddress((void**)&p_hs,  g_hs);
    cudaGetSymbolAddress((void**)&p_h1,  g_h1);
    cudaGetSymbolAddress((void**)&p_h3,  g_h3);
    cudaGetSymbolAddress((void**)&p_hh,  g_hh);

    cudaFuncSetAttribute(tc_gemm<0>, cudaFuncAttributeMaxDynamicSharedMemorySize, DSM);
    cudaFuncSetAttribute(tc_gemm<1>, cudaFuncAttributeMaxDynamicSharedMemorySize, DSM);
    cudaFuncSetAttribute(tc_gemm<2>, cudaFuncAttributeMaxDynamicSharedMemorySize, DSM);
    cudaFuncSetAttribute(tc_gemm<3>, cudaFuncAttributeMaxDynamicSharedMemorySize, DSM);

    QKV3 zero3 = {};
    QKV3 qkv;
    qkv.B[0] = wq_w; qkv.B[1] = wk_w; qkv.B[2] = wv_w;
    qkv.Bb[0] = wq_b; qkv.Bb[1] = wk_b; qkv.Bb[2] = wv_b;
    qkv.C[0] = p_q; qkv.C[1] = p_k; qkv.C[2] = p_v;

    // attention
    ln_kernel<<<SQ, 256>>>(x, attn_g, p_ln);
    tc_gemm<3><<<dim3(HDIM/128, SQ/128, 3), 256, DSM>>>(p_ln, nullptr, nullptr, nullptr,
                                                        nullptr, HDIM, DM, qkv);
    score_kernel<<<dim3(SQ/64, SQ/64, NH), 256>>>(mask);
    softmax_kernel<<<NH*SQ, 256>>>();
    pv_kernel<<<dim3(DKV/64, SQ/64, NH), 256>>>();
    tc_gemm<0><<<dim3(DM/128, SQ/128), 256, DSM>>>(p_attn, wo_w, wo_b, x, p_x2, DM, HDIM, zero3);

    // moe routing
    ln_kernel<<<SQ, 256>>>(p_x2, ffn_g, p_ln2);
    reset_kernel<<<1, 32>>>();
    gate_kernel<<<SQ, 256>>>(p_ln2, gate_w, gate_b);
    scan_kernel<<<1, 1>>>();
    place_kernel<<<(SQ+255)/256, 256>>>();

    // shared expert
    tc_gemm<0><<<dim3(FSH/128, SQ/128), 256, DSM>>>(p_ln2, s_w1, s_b1, nullptr, p_t1, FSH, DM, zero3);
    tc_gemm<0><<<dim3(FSH/128, SQ/128), 256, DSM>>>(p_ln2, s_w3, s_b3, nullptr, p_t3, FSH, DM, zero3);
    silu_mul_kernel<<<(SQ*FSH/4+255)/256, 256>>>(p_t1, p_t3, p_hs, SQ*FSH/4);
    tc_gemm<0><<<dim3(DM/128, SQ/128), 256, DSM>>>(p_hs, s_w2, s_b2, p_x2, outp, DM, FSH, zero3);

    // routed experts
    tc_gemm<1><<<dim3(FF/128, SQ/128, NE), 256, DSM>>>(p_ln2, e_w1, e_b1, nullptr, p_h1, FF, DM, zero3);
    tc_gemm<1><<<dim3(FF/128, SQ/128, NE), 256, DSM>>>(p_ln2, e_w3, e_b3, nullptr, p_h3, FF, DM, zero3);
    silu_mul_kernel<<<(NSLOT*FF/4+255)/256, 256>>>(p_h1, p_h3, p_hh, NSLOT*FF/4);
    tc_gemm<2><<<dim3(DM/128, SQ/128, NE), 256, DSM>>>(p_hh, e_w2, e_b2, nullptr, outp, DM, FF, zero3);
}